// round 1
// baseline (speedup 1.0000x reference)
#include <cuda_runtime.h>

#define N_NODES 50000
#define N_EDGES 800000
#define F_IN    256
#define NH      4
#define HD      64   // NH * 16
#define DPH     16

// Scratch (device globals; no allocations allowed)
__device__ float    g_hsrc[N_NODES * HD];   // feat @ W_src^T + b_src
__device__ float    g_hdst[N_NODES * HD];   // feat @ W_dst^T + b_dst
__device__ float    g_score[N_EDGES * NH];  // per-(edge,head) score, then exp()
__device__ unsigned g_m[N_NODES * NH];      // segment max (ordered-uint encoded)
__device__ float    g_s[N_NODES * NH];      // segment sum

// ---- ordered-uint encoding for float atomicMax ----
__device__ __forceinline__ unsigned enc_f(float f) {
    unsigned u = __float_as_uint(f);
    return (u & 0x80000000u) ? ~u : (u | 0x80000000u);
}
__device__ __forceinline__ float dec_f(unsigned u) {
    u = (u & 0x80000000u) ? (u & 0x7FFFFFFFu) : ~u;
    return __uint_as_float(u);
}

__global__ void init_kernel() {
    int i = blockIdx.x * blockDim.x + threadIdx.x;
    if (i < N_NODES * NH) {
        g_m[i] = 0x007FFFFFu;  // enc(-inf)
        g_s[i] = 0.0f;
    }
}

// ---- Fused projection GEMM: out[n, o] = dot(feat[n,:], Wcat[o,:]) + bcat[o]
// Wcat = concat(W_src, W_dst) rows (128 x 256). BM=128, BN=128, BK=16,
// 256 threads, 8x8 micro-tile per thread.
__global__ __launch_bounds__(256) void proj_kernel(
    const float* __restrict__ feat,
    const float* __restrict__ Wsrc, const float* __restrict__ bsrc,
    const float* __restrict__ Wdst, const float* __restrict__ bdst)
{
    __shared__ float As[16][132];  // [k][m], +4 pad keeps 16B alignment, avoids conflicts
    __shared__ float Bs[16][128];  // [k][o]

    const int tid = threadIdx.x;
    const int m0  = blockIdx.x * 128;
    const int tm  = (tid >> 4) * 8;   // 0..120
    const int tn  = (tid & 15) * 8;   // 0..120

    float acc[8][8];
    #pragma unroll
    for (int i = 0; i < 8; i++)
        #pragma unroll
        for (int j = 0; j < 8; j++) acc[i][j] = 0.0f;

    const int lr = tid >> 2;   // 0..63
    const int c4 = tid & 3;    // 0..3 (float4 group within 16 k-cols)

    for (int k0 = 0; k0 < F_IN; k0 += 16) {
        // load A tile (128 rows x 16 k) : 2 float4 per thread
        #pragma unroll
        for (int i = 0; i < 2; i++) {
            int r  = lr + i * 64;
            int gr = m0 + r;
            float4 v = make_float4(0.f, 0.f, 0.f, 0.f);
            if (gr < N_NODES)
                v = *(const float4*)(feat + (size_t)gr * F_IN + k0 + c4 * 4);
            As[c4 * 4 + 0][r] = v.x;
            As[c4 * 4 + 1][r] = v.y;
            As[c4 * 4 + 2][r] = v.z;
            As[c4 * 4 + 3][r] = v.w;
        }
        // load B tile (128 outs x 16 k)
        #pragma unroll
        for (int i = 0; i < 2; i++) {
            int o = lr + i * 64;
            const float* Wrow = (o < 64) ? (Wsrc + (size_t)o * F_IN)
                                         : (Wdst + (size_t)(o - 64) * F_IN);
            float4 v = *(const float4*)(Wrow + k0 + c4 * 4);
            Bs[c4 * 4 + 0][o] = v.x;
            Bs[c4 * 4 + 1][o] = v.y;
            Bs[c4 * 4 + 2][o] = v.z;
            Bs[c4 * 4 + 3][o] = v.w;
        }
        __syncthreads();

        #pragma unroll
        for (int k = 0; k < 16; k++) {
            float a[8], b[8];
            #pragma unroll
            for (int i = 0; i < 8; i++) a[i] = As[k][tm + i];
            #pragma unroll
            for (int j = 0; j < 8; j++) b[j] = Bs[k][tn + j];
            #pragma unroll
            for (int i = 0; i < 8; i++)
                #pragma unroll
                for (int j = 0; j < 8; j++) acc[i][j] += a[i] * b[j];
        }
        __syncthreads();
    }

    // epilogue: add bias, write to hsrc / hdst
    #pragma unroll
    for (int i = 0; i < 8; i++) {
        int gr = m0 + tm + i;
        if (gr < N_NODES) {
            #pragma unroll
            for (int j = 0; j < 8; j++) {
                int o = tn + j;
                float v = acc[i][j];
                if (o < 64) g_hsrc[(size_t)gr * HD + o]        = v + bsrc[o];
                else        g_hdst[(size_t)gr * HD + (o - 64)] = v + bdst[o - 64];
            }
        }
    }
}

// ---- Pass 1: per-(edge, head) attention logit + segment max
__global__ __launch_bounds__(256) void edge_score_kernel(
    const int* __restrict__ src, const int* __restrict__ dst,
    const float* __restrict__ attn)
{
    int idx = blockIdx.x * blockDim.x + threadIdx.x;
    if (idx >= N_EDGES * NH) return;
    int e = idx >> 2, h = idx & 3;
    int sn = src[e], dn = dst[e];

    const float4* elp = (const float4*)(g_hsrc + (size_t)sn * HD + h * DPH);
    const float4* erp = (const float4*)(g_hdst + (size_t)dn * HD + h * DPH);
    const float4* ap  = (const float4*)(attn + h * DPH);

    float acc = 0.0f;
    #pragma unroll
    for (int j = 0; j < 4; j++) {
        float4 a = elp[j], b = erp[j], w = ap[j];
        float v;
        v = a.x + b.x; v = (v > 0.f) ? v : 0.2f * v; acc += v * w.x;
        v = a.y + b.y; v = (v > 0.f) ? v : 0.2f * v; acc += v * w.y;
        v = a.z + b.z; v = (v > 0.f) ? v : 0.2f * v; acc += v * w.z;
        v = a.w + b.w; v = (v > 0.f) ? v : 0.2f * v; acc += v * w.w;
    }
    g_score[idx] = acc;
    atomicMax(&g_m[dn * NH + h], enc_f(acc));
}

// ---- Pass 2: a = exp(score - m[dst]); segment sum
__global__ __launch_bounds__(256) void edge_exp_kernel(const int* __restrict__ dst)
{
    int idx = blockIdx.x * blockDim.x + threadIdx.x;
    if (idx >= N_EDGES * NH) return;
    int e = idx >> 2, h = idx & 3;
    int dn = dst[e];
    float m = dec_f(g_m[dn * NH + h]);
    float a = __expf(g_score[idx] - m);
    g_score[idx] = a;
    atomicAdd(&g_s[dn * NH + h], a);
}

// ---- Pass 3: alpha = a / s[dst]; scatter-accumulate alpha * el into out
__global__ __launch_bounds__(256) void edge_agg_kernel(
    const int* __restrict__ src, const int* __restrict__ dst,
    float* __restrict__ out)
{
    int idx = blockIdx.x * blockDim.x + threadIdx.x;
    if (idx >= N_EDGES * NH) return;
    int e = idx >> 2, h = idx & 3;
    int sn = src[e], dn = dst[e];

    float alpha = g_score[idx] / g_s[dn * NH + h];
    const float4* elp = (const float4*)(g_hsrc + (size_t)sn * HD + h * DPH);
    float* ob = out + (size_t)dn * HD + h * DPH;
    #pragma unroll
    for (int j = 0; j < 4; j++) {
        float4 a = elp[j];
        atomicAdd(ob + 4 * j + 0, alpha * a.x);
        atomicAdd(ob + 4 * j + 1, alpha * a.y);
        atomicAdd(ob + 4 * j + 2, alpha * a.z);
        atomicAdd(ob + 4 * j + 3, alpha * a.w);
    }
}

extern "C" void kernel_launch(void* const* d_in, const int* in_sizes, int n_in,
                              void* d_out, int out_size)
{
    const float* feat = (const float*)d_in[0];
    const int*   src  = (const int*)d_in[1];
    const int*   dst  = (const int*)d_in[2];
    const float* Wsrc = (const float*)d_in[3];
    const float* bsrc = (const float*)d_in[4];
    const float* Wdst = (const float*)d_in[5];
    const float* bdst = (const float*)d_in[6];
    const float* attn = (const float*)d_in[7];
    float* out = (float*)d_out;

    cudaMemsetAsync(out, 0, (size_t)out_size * sizeof(float));
    init_kernel<<<(N_NODES * NH + 255) / 256, 256>>>();
    proj_kernel<<<(N_NODES + 127) / 128, 256>>>(feat, Wsrc, bsrc, Wdst, bdst);

    const int eb = (N_EDGES * NH + 255) / 256;
    edge_score_kernel<<<eb, 256>>>(src, dst, attn);
    edge_exp_kernel<<<eb, 256>>>(dst);
    edge_agg_kernel<<<eb, 256>>>(src, dst, out);
}

// round 2
// speedup vs baseline: 1.4909x; 1.4909x over previous
#include <cuda_runtime.h>

#define N_NODES 50000
#define N_EDGES 800000
#define F_IN    256
#define NH      4
#define HD      64   // NH * 16
#define DPH     16

// Scratch (device globals; no allocations allowed)
__device__ float g_hsrc[N_NODES * HD];   // feat @ W_src^T + b_src
__device__ float g_hdst[N_NODES * HD];   // feat @ W_dst^T + b_dst
__device__ float g_s[N_NODES * NH];      // sum of exp(score) per (node, head)

__device__ __forceinline__ void red_add_v4(float* p, float x, float y, float z, float w) {
    asm volatile("red.global.add.v4.f32 [%0], {%1, %2, %3, %4};"
                 :: "l"(p), "f"(x), "f"(y), "f"(z), "f"(w) : "memory");
}

__global__ void init_kernel() {
    int i = blockIdx.x * blockDim.x + threadIdx.x;
    if (i < N_NODES * NH) g_s[i] = 0.0f;
}

// ---- Fused projection GEMM: out[n, o] = dot(feat[n,:], Wcat[o,:]) + bcat[o]
// Wcat = concat(W_src, W_dst) rows (128 x 256). BM=128, BN=128, BK=16,
// 256 threads, 8x8 micro-tile per thread.
__global__ __launch_bounds__(256) void proj_kernel(
    const float* __restrict__ feat,
    const float* __restrict__ Wsrc, const float* __restrict__ bsrc,
    const float* __restrict__ Wdst, const float* __restrict__ bdst)
{
    __shared__ float As[16][132];
    __shared__ float Bs[16][128];

    const int tid = threadIdx.x;
    const int m0  = blockIdx.x * 128;
    const int tm  = (tid >> 4) * 8;
    const int tn  = (tid & 15) * 8;

    float acc[8][8];
    #pragma unroll
    for (int i = 0; i < 8; i++)
        #pragma unroll
        for (int j = 0; j < 8; j++) acc[i][j] = 0.0f;

    const int lr = tid >> 2;
    const int c4 = tid & 3;

    for (int k0 = 0; k0 < F_IN; k0 += 16) {
        #pragma unroll
        for (int i = 0; i < 2; i++) {
            int r  = lr + i * 64;
            int gr = m0 + r;
            float4 v = make_float4(0.f, 0.f, 0.f, 0.f);
            if (gr < N_NODES)
                v = *(const float4*)(feat + (size_t)gr * F_IN + k0 + c4 * 4);
            As[c4 * 4 + 0][r] = v.x;
            As[c4 * 4 + 1][r] = v.y;
            As[c4 * 4 + 2][r] = v.z;
            As[c4 * 4 + 3][r] = v.w;
        }
        #pragma unroll
        for (int i = 0; i < 2; i++) {
            int o = lr + i * 64;
            const float* Wrow = (o < 64) ? (Wsrc + (size_t)o * F_IN)
                                         : (Wdst + (size_t)(o - 64) * F_IN);
            float4 v = *(const float4*)(Wrow + k0 + c4 * 4);
            Bs[c4 * 4 + 0][o] = v.x;
            Bs[c4 * 4 + 1][o] = v.y;
            Bs[c4 * 4 + 2][o] = v.z;
            Bs[c4 * 4 + 3][o] = v.w;
        }
        __syncthreads();

        #pragma unroll
        for (int k = 0; k < 16; k++) {
            float a[8], b[8];
            #pragma unroll
            for (int i = 0; i < 8; i++) a[i] = As[k][tm + i];
            #pragma unroll
            for (int j = 0; j < 8; j++) b[j] = Bs[k][tn + j];
            #pragma unroll
            for (int i = 0; i < 8; i++)
                #pragma unroll
                for (int j = 0; j < 8; j++) acc[i][j] += a[i] * b[j];
        }
        __syncthreads();
    }

    #pragma unroll
    for (int i = 0; i < 8; i++) {
        int gr = m0 + tm + i;
        if (gr < N_NODES) {
            #pragma unroll
            for (int j = 0; j < 8; j++) {
                int o = tn + j;
                float v = acc[i][j];
                if (o < 64) g_hsrc[(size_t)gr * HD + o]        = v + bsrc[o];
                else        g_hdst[(size_t)gr * HD + (o - 64)] = v + bdst[o - 64];
            }
        }
    }
}

// ---- Fused edge kernel: one thread per edge, all 4 heads.
// score = dot(leakyrelu(el + er), attn);  a = exp(score)   (no max shift)
// out[dst] += a * el  (unnormalized);     s[dst,h] += a
__global__ __launch_bounds__(256) void edge_fused_kernel(
    const int* __restrict__ src, const int* __restrict__ dst,
    const float* __restrict__ attn, float* __restrict__ out)
{
    int e = blockIdx.x * blockDim.x + threadIdx.x;
    if (e >= N_EDGES) return;
    int sn = src[e], dn = dst[e];

    const float4* elp = (const float4*)(g_hsrc + (size_t)sn * HD);
    const float4* erp = (const float4*)(g_hdst + (size_t)dn * HD);
    const float4* ap  = (const float4*)attn;
    float* ob = out + (size_t)dn * HD;

    float a_h[NH];

    #pragma unroll
    for (int h = 0; h < NH; h++) {
        float4 el[4], er[4];
        #pragma unroll
        for (int j = 0; j < 4; j++) {
            el[j] = elp[h * 4 + j];
            er[j] = erp[h * 4 + j];
        }
        float acc = 0.0f;
        #pragma unroll
        for (int j = 0; j < 4; j++) {
            float4 w = ap[h * 4 + j];
            float v;
            v = el[j].x + er[j].x; v = (v > 0.f) ? v : 0.2f * v; acc += v * w.x;
            v = el[j].y + er[j].y; v = (v > 0.f) ? v : 0.2f * v; acc += v * w.y;
            v = el[j].z + er[j].z; v = (v > 0.f) ? v : 0.2f * v; acc += v * w.z;
            v = el[j].w + er[j].w; v = (v > 0.f) ? v : 0.2f * v; acc += v * w.w;
        }
        float a = __expf(acc);
        a_h[h] = a;
        #pragma unroll
        for (int j = 0; j < 4; j++) {
            red_add_v4(ob + h * DPH + 4 * j,
                       a * el[j].x, a * el[j].y, a * el[j].z, a * el[j].w);
        }
    }
    red_add_v4(g_s + (size_t)dn * NH, a_h[0], a_h[1], a_h[2], a_h[3]);
}

// ---- Normalize: out[n, h, :] /= s[n, h]
__global__ __launch_bounds__(256) void normalize_kernel(float* __restrict__ out)
{
    int idx = blockIdx.x * blockDim.x + threadIdx.x;   // over N*NH
    if (idx >= N_NODES * NH) return;
    float s = g_s[idx];
    if (s == 0.0f) return;   // isolated node: out already 0
    float inv = 1.0f / s;
    float4* ob = (float4*)(out + (size_t)idx * DPH);
    #pragma unroll
    for (int j = 0; j < 4; j++) {
        float4 v = ob[j];
        v.x *= inv; v.y *= inv; v.z *= inv; v.w *= inv;
        ob[j] = v;
    }
}

extern "C" void kernel_launch(void* const* d_in, const int* in_sizes, int n_in,
                              void* d_out, int out_size)
{
    const float* feat = (const float*)d_in[0];
    const int*   src  = (const int*)d_in[1];
    const int*   dst  = (const int*)d_in[2];
    const float* Wsrc = (const float*)d_in[3];
    const float* bsrc = (const float*)d_in[4];
    const float* Wdst = (const float*)d_in[5];
    const float* bdst = (const float*)d_in[6];
    const float* attn = (const float*)d_in[7];
    float* out = (float*)d_out;

    cudaMemsetAsync(out, 0, (size_t)out_size * sizeof(float));
    init_kernel<<<(N_NODES * NH + 255) / 256, 256>>>();
    proj_kernel<<<(N_NODES + 127) / 128, 256>>>(feat, Wsrc, bsrc, Wdst, bdst);
    edge_fused_kernel<<<(N_EDGES + 255) / 256, 256>>>(src, dst, attn, out);
    normalize_kernel<<<(N_NODES * NH + 255) / 256, 256>>>(out);
}

// round 3
// speedup vs baseline: 1.6615x; 1.1145x over previous
#include <cuda_runtime.h>

#define N_NODES 50000
#define N_EDGES 800000
#define F_IN    256
#define NH      4
#define HD      64   // NH * 16
#define DPH     16

// Scratch (device globals; no allocations allowed)
__device__ float g_hsrc[N_NODES * HD];   // feat @ W_src^T + b_src
__device__ float g_hdst[N_NODES * HD];   // feat @ W_dst^T + b_dst
__device__ int   g_deg[N_NODES];         // in-degree
__device__ int   g_ptr[N_NODES];         // CSR row start (exclusive prefix of deg)
__device__ int   g_cur[N_NODES];         // scatter cursor (copy of g_ptr)
__device__ int   g_asrc[N_EDGES];        // CSR payload: src node id per incoming edge

__global__ void init_deg_kernel() {
    int i = blockIdx.x * blockDim.x + threadIdx.x;
    if (i < N_NODES) g_deg[i] = 0;
}

__global__ void hist_kernel(const int* __restrict__ dst) {
    int e = blockIdx.x * blockDim.x + threadIdx.x;
    if (e < N_EDGES) atomicAdd(&g_deg[dst[e]], 1);
}

// Single-block exclusive scan of g_deg -> g_ptr, g_cur. 1024 threads.
#define SCAN_T 1024
#define SCAN_CHUNK 49   // 1024*49 = 50176 >= 50000
__global__ __launch_bounds__(SCAN_T) void scan_kernel() {
    __shared__ int sm[SCAN_T];
    int t = threadIdx.x;
    int lo = t * SCAN_CHUNK;
    int hi = lo + SCAN_CHUNK; if (hi > N_NODES) hi = N_NODES;

    int sum = 0;
    for (int i = lo; i < hi; i++) sum += g_deg[i];
    sm[t] = sum;
    __syncthreads();
    // Hillis-Steele inclusive scan over 1024 partials
    for (int off = 1; off < SCAN_T; off <<= 1) {
        int v = (t >= off) ? sm[t - off] : 0;
        __syncthreads();
        sm[t] += v;
        __syncthreads();
    }
    int run = (t > 0) ? sm[t - 1] : 0;   // exclusive prefix of this chunk
    for (int i = lo; i < hi; i++) {
        g_ptr[i] = run;
        g_cur[i] = run;
        run += g_deg[i];
    }
}

__global__ void scatter_kernel(const int* __restrict__ src, const int* __restrict__ dst) {
    int e = blockIdx.x * blockDim.x + threadIdx.x;
    if (e >= N_EDGES) return;
    int pos = atomicAdd(&g_cur[dst[e]], 1);
    g_asrc[pos] = src[e];
}

// ---- Fused projection GEMM: out[n, o] = dot(feat[n,:], Wcat[o,:]) + bcat[o]
__global__ __launch_bounds__(256) void proj_kernel(
    const float* __restrict__ feat,
    const float* __restrict__ Wsrc, const float* __restrict__ bsrc,
    const float* __restrict__ Wdst, const float* __restrict__ bdst)
{
    __shared__ float As[16][132];
    __shared__ float Bs[16][128];

    const int tid = threadIdx.x;
    const int m0  = blockIdx.x * 128;
    const int tm  = (tid >> 4) * 8;
    const int tn  = (tid & 15) * 8;

    float acc[8][8];
    #pragma unroll
    for (int i = 0; i < 8; i++)
        #pragma unroll
        for (int j = 0; j < 8; j++) acc[i][j] = 0.0f;

    const int lr = tid >> 2;
    const int c4 = tid & 3;

    for (int k0 = 0; k0 < F_IN; k0 += 16) {
        #pragma unroll
        for (int i = 0; i < 2; i++) {
            int r  = lr + i * 64;
            int gr = m0 + r;
            float4 v = make_float4(0.f, 0.f, 0.f, 0.f);
            if (gr < N_NODES)
                v = *(const float4*)(feat + (size_t)gr * F_IN + k0 + c4 * 4);
            As[c4 * 4 + 0][r] = v.x;
            As[c4 * 4 + 1][r] = v.y;
            As[c4 * 4 + 2][r] = v.z;
            As[c4 * 4 + 3][r] = v.w;
        }
        #pragma unroll
        for (int i = 0; i < 2; i++) {
            int o = lr + i * 64;
            const float* Wrow = (o < 64) ? (Wsrc + (size_t)o * F_IN)
                                         : (Wdst + (size_t)(o - 64) * F_IN);
            float4 v = *(const float4*)(Wrow + k0 + c4 * 4);
            Bs[c4 * 4 + 0][o] = v.x;
            Bs[c4 * 4 + 1][o] = v.y;
            Bs[c4 * 4 + 2][o] = v.z;
            Bs[c4 * 4 + 3][o] = v.w;
        }
        __syncthreads();

        #pragma unroll
        for (int k = 0; k < 16; k++) {
            float a[8], b[8];
            #pragma unroll
            for (int i = 0; i < 8; i++) a[i] = As[k][tm + i];
            #pragma unroll
            for (int j = 0; j < 8; j++) b[j] = Bs[k][tn + j];
            #pragma unroll
            for (int i = 0; i < 8; i++)
                #pragma unroll
                for (int j = 0; j < 8; j++) acc[i][j] += a[i] * b[j];
        }
        __syncthreads();
    }

    #pragma unroll
    for (int i = 0; i < 8; i++) {
        int gr = m0 + tm + i;
        if (gr < N_NODES) {
            #pragma unroll
            for (int j = 0; j < 8; j++) {
                int o = tn + j;
                float v = acc[i][j];
                if (o < 64) g_hsrc[(size_t)gr * HD + o]        = v + bsrc[o];
                else        g_hdst[(size_t)gr * HD + (o - 64)] = v + bdst[o - 64];
            }
        }
    }
}

// ---- Aggregation: one warp per destination node. No atomics anywhere.
// lane owns output dims {2*lane, 2*lane+1}; head = lane>>3.
__global__ __launch_bounds__(256) void agg_kernel(float* __restrict__ out,
                                                  const float* __restrict__ attn)
{
    int warp = (blockIdx.x * blockDim.x + threadIdx.x) >> 5;
    int lane = threadIdx.x & 31;
    if (warp >= N_NODES) return;
    const int d = warp;

    float2 er = ((const float2*)(g_hdst + (size_t)d * HD))[lane];
    float2 aw = ((const float2*)attn)[lane];

    const int start = g_ptr[d];
    const int cnt   = g_deg[d];

    float2 acc = make_float2(0.f, 0.f);
    float  s   = 0.f;

    for (int base = 0; base < cnt; base += 32) {
        int m = cnt - base; if (m > 32) m = 32;
        int sn_l = (lane < m) ? g_asrc[start + base + lane] : 0;
        for (int i = 0; i < m; i++) {
            int sn = __shfl_sync(0xFFFFFFFFu, sn_l, i);
            float2 el = ((const float2*)(g_hsrc + (size_t)sn * HD))[lane];
            float vx = el.x + er.x; vx = (vx > 0.f) ? vx : 0.2f * vx;
            float vy = el.y + er.y; vy = (vy > 0.f) ? vy : 0.2f * vy;
            float p  = vx * aw.x + vy * aw.y;
            // reduce partial dot over the 8 lanes of this head
            p += __shfl_xor_sync(0xFFFFFFFFu, p, 1);
            p += __shfl_xor_sync(0xFFFFFFFFu, p, 2);
            p += __shfl_xor_sync(0xFFFFFFFFu, p, 4);
            float a = __expf(p);
            acc.x += a * el.x;
            acc.y += a * el.y;
            s     += a;
        }
    }

    float inv = (s > 0.f) ? (1.f / s) : 0.f;
    float2 o = make_float2(acc.x * inv, acc.y * inv);
    ((float2*)(out + (size_t)d * HD))[lane] = o;
}

extern "C" void kernel_launch(void* const* d_in, const int* in_sizes, int n_in,
                              void* d_out, int out_size)
{
    const float* feat = (const float*)d_in[0];
    const int*   src  = (const int*)d_in[1];
    const int*   dst  = (const int*)d_in[2];
    const float* Wsrc = (const float*)d_in[3];
    const float* bsrc = (const float*)d_in[4];
    const float* Wdst = (const float*)d_in[5];
    const float* bdst = (const float*)d_in[6];
    const float* attn = (const float*)d_in[7];
    float* out = (float*)d_out;

    init_deg_kernel<<<(N_NODES + 255) / 256, 256>>>();
    hist_kernel<<<(N_EDGES + 255) / 256, 256>>>(dst);
    scan_kernel<<<1, SCAN_T>>>();
    scatter_kernel<<<(N_EDGES + 255) / 256, 256>>>(src, dst);
    proj_kernel<<<(N_NODES + 127) / 128, 256>>>(feat, Wsrc, bsrc, Wdst, bdst);
    agg_kernel<<<(N_NODES * 32 + 255) / 256, 256>>>(out, attn);
}

// round 5
// speedup vs baseline: 2.2405x; 1.3485x over previous
#include <cuda_runtime.h>
#include <cuda_bf16.h>
#include <cstdint>

#define N_NODES 50000
#define N_EDGES 800000
#define F_IN    256
#define NH      4
#define HD      64

// ---------------- scratch (device globals; no allocs allowed) ----------------
__device__ float g_hsrc[N_NODES * HD];
__device__ float g_hdst[N_NODES * HD];
__device__ int   g_deg[N_NODES];
__device__ int   g_ptr[N_NODES];
__device__ int   g_cur[N_NODES];
__device__ int   g_asrc[N_EDGES];

// ---------------- CSR build ----------------
__global__ void init_deg_kernel() {
    int i = blockIdx.x * blockDim.x + threadIdx.x;
    if (i < N_NODES) g_deg[i] = 0;
}
__global__ void hist_kernel(const int* __restrict__ dst) {
    int e = blockIdx.x * blockDim.x + threadIdx.x;
    if (e < N_EDGES) atomicAdd(&g_deg[dst[e]], 1);
}
#define SCAN_T 1024
#define SCAN_CHUNK 49
__global__ __launch_bounds__(SCAN_T) void scan_kernel() {
    __shared__ int sm[SCAN_T];
    int t = threadIdx.x;
    int lo = t * SCAN_CHUNK;
    int hi = lo + SCAN_CHUNK; if (hi > N_NODES) hi = N_NODES;
    int sum = 0;
    for (int i = lo; i < hi; i++) sum += g_deg[i];
    sm[t] = sum;
    __syncthreads();
    for (int off = 1; off < SCAN_T; off <<= 1) {
        int v = (t >= off) ? sm[t - off] : 0;
        __syncthreads();
        sm[t] += v;
        __syncthreads();
    }
    int run = (t > 0) ? sm[t - 1] : 0;
    for (int i = lo; i < hi; i++) {
        g_ptr[i] = run; g_cur[i] = run;
        run += g_deg[i];
    }
}
__global__ void scatter_kernel(const int* __restrict__ src, const int* __restrict__ dst) {
    int e = blockIdx.x * blockDim.x + threadIdx.x;
    if (e >= N_EDGES) return;
    int pos = atomicAdd(&g_cur[dst[e]], 1);
    g_asrc[pos] = src[e];
}

// ---------------- helpers ----------------
__device__ __forceinline__ uint32_t smem_u32(const void* p) {
    uint32_t a;
    asm("{ .reg .u64 t; cvta.to.shared.u64 t, %1; cvt.u32.u64 %0, t; }" : "=r"(a) : "l"(p));
    return a;
}
__device__ __forceinline__ void ldsm4(unsigned r[4], uint32_t a) {
    asm volatile("ldmatrix.sync.aligned.m8n8.x4.shared.b16 {%0,%1,%2,%3}, [%4];"
                 : "=r"(r[0]), "=r"(r[1]), "=r"(r[2]), "=r"(r[3]) : "r"(a));
}
__device__ __forceinline__ void mma_bf16(float c[4], const unsigned a[4], const unsigned b[2]) {
    asm volatile(
        "mma.sync.aligned.m16n8k16.row.col.f32.bf16.bf16.f32 "
        "{%0,%1,%2,%3}, {%4,%5,%6,%7}, {%8,%9}, {%0,%1,%2,%3};"
        : "+f"(c[0]), "+f"(c[1]), "+f"(c[2]), "+f"(c[3])
        : "r"(a[0]), "r"(a[1]), "r"(a[2]), "r"(a[3]), "r"(b[0]), "r"(b[1]));
}
__device__ __forceinline__ void cvt8(float4 a, float4 b, uint4& hi, uint4& lo) {
    float xs[8] = {a.x, a.y, a.z, a.w, b.x, b.y, b.z, b.w};
    unsigned h[4], l[4];
    #pragma unroll
    for (int i = 0; i < 4; i++) {
        float x = xs[2 * i], y = xs[2 * i + 1];
        __nv_bfloat16 hx = __float2bfloat16_rn(x);
        __nv_bfloat16 hy = __float2bfloat16_rn(y);
        __nv_bfloat16 lx = __float2bfloat16_rn(x - __bfloat162float(hx));
        __nv_bfloat16 ly = __float2bfloat16_rn(y - __bfloat162float(hy));
        unsigned short uhx = *(unsigned short*)&hx, uhy = *(unsigned short*)&hy;
        unsigned short ulx = *(unsigned short*)&lx, uly = *(unsigned short*)&ly;
        h[i] = (unsigned)uhx | ((unsigned)uhy << 16);
        l[i] = (unsigned)ulx | ((unsigned)uly << 16);
    }
    hi = make_uint4(h[0], h[1], h[2], h[3]);
    lo = make_uint4(l[0], l[1], l[2], l[3]);
}

// ---------------- HMMA bf16-split projection GEMM ----------------
// Per CTA: D[128 nodes x 128 outs], K=256 in 4 chunks of 64.
// SMEM tiles: 128 rows x 64 bf16, padded row stride 72 elems (144 B).
#define RSB    144
#define SA_HI  0
#define SA_LO  18432
#define SB_HI  36864
#define SB_LO  55296
#define SM_TOT 73728

__global__ __launch_bounds__(256, 1)
void proj_mma_kernel(const float* __restrict__ feat,
                     const float* __restrict__ Wsrc, const float* __restrict__ bsrc,
                     const float* __restrict__ Wdst, const float* __restrict__ bdst)
{
    extern __shared__ char smem[];
    const uint32_t sb = smem_u32(smem);
    const int tid  = threadIdx.x;
    const int wid  = tid >> 5, lane = tid & 31;
    const int warp_m = wid & 3;   // 0..3 -> rows warp_m*32
    const int warp_n = wid >> 2;  // 0..1 -> cols warp_n*64
    const int m0 = blockIdx.x * 128;

    float acc[2][8][4];
    #pragma unroll
    for (int mt = 0; mt < 2; mt++)
        #pragma unroll
        for (int nt = 0; nt < 8; nt++)
            #pragma unroll
            for (int j = 0; j < 4; j++) acc[mt][nt][j] = 0.0f;

    // load-task decomposition: 1024 tasks (128 rows x 8 segs of 8 floats), 4 per thread
    float4 pa[4][2], pb[4][2];

    #define LOAD_A(c) do {                                                        \
        _Pragma("unroll")                                                         \
        for (int i = 0; i < 4; i++) {                                             \
            int t = tid + i * 256, row = t >> 3, seg = t & 7;                     \
            int node = m0 + row; if (node >= N_NODES) node = N_NODES - 1;         \
            const float* p = feat + (size_t)node * F_IN + (c) * 64 + seg * 8;     \
            pa[i][0] = *(const float4*)p; pa[i][1] = *(const float4*)(p + 4);     \
        } } while (0)

    #define LOAD_B(c) do {                                                        \
        _Pragma("unroll")                                                         \
        for (int i = 0; i < 4; i++) {                                             \
            int t = tid + i * 256, row = t >> 3, seg = t & 7;                     \
            const float* wr = (row < 64) ? (Wsrc + (size_t)row * F_IN)            \
                                         : (Wdst + (size_t)(row - 64) * F_IN);    \
            const float* p = wr + (c) * 64 + seg * 8;                             \
            pb[i][0] = *(const float4*)p; pb[i][1] = *(const float4*)(p + 4);     \
        } } while (0)

    #define STORE_AB() do {                                                       \
        _Pragma("unroll")                                                         \
        for (int i = 0; i < 4; i++) {                                             \
            int t = tid + i * 256, row = t >> 3, seg = t & 7;                     \
            uint32_t off = (uint32_t)(row * RSB + seg * 16);                      \
            uint4 hi, lo;                                                         \
            cvt8(pa[i][0], pa[i][1], hi, lo);                                     \
            *(uint4*)(smem + SA_HI + off) = hi;                                   \
            *(uint4*)(smem + SA_LO + off) = lo;                                   \
            cvt8(pb[i][0], pb[i][1], hi, lo);                                     \
            *(uint4*)(smem + SB_HI + off) = hi;                                   \
            *(uint4*)(smem + SB_LO + off) = lo;                                   \
        } } while (0)

    LOAD_A(0); LOAD_B(0);
    STORE_AB();
    __syncthreads();

    // ldmatrix base addresses (per thread)
    // A: row = warp_m*32 + mt*16 + (lane&15); kbyte = ks*32 + (lane>>4)*16
    const uint32_t a_base = sb + SA_HI +
        (uint32_t)((warp_m * 32 + (lane & 15)) * RSB + (lane >> 4) * 16);
    // B: n-row = warp_n*64 + p*16 + (lane&7) + (lane>>4)*8; kbyte = ks*32 + ((lane>>3)&1)*16
    const uint32_t b_base = sb + SB_HI +
        (uint32_t)((warp_n * 64 + (lane & 7) + ((lane >> 4) & 1) * 8) * RSB +
                   ((lane >> 3) & 1) * 16);

    for (int c = 0; c < 4; c++) {
        if (c < 3) { LOAD_A(c + 1); LOAD_B(c + 1); }   // prefetch overlaps MMA below

        #pragma unroll
        for (int ks = 0; ks < 4; ks++) {
            unsigned ah[2][4], al[2][4];
            #pragma unroll
            for (int mt = 0; mt < 2; mt++) {
                ldsm4(ah[mt], a_base + (uint32_t)(mt * 16 * RSB + ks * 32));
                ldsm4(al[mt], a_base + (uint32_t)(18432 + mt * 16 * RSB + ks * 32));
            }
            unsigned bh[4][4], bl[4][4];
            #pragma unroll
            for (int p = 0; p < 4; p++) {
                ldsm4(bh[p], b_base + (uint32_t)(p * 16 * RSB + ks * 32));
                ldsm4(bl[p], b_base + (uint32_t)(18432 + p * 16 * RSB + ks * 32));
            }
            #pragma unroll
            for (int mt = 0; mt < 2; mt++)
                #pragma unroll
                for (int nt = 0; nt < 8; nt++) {
                    const unsigned* bhf = &bh[nt >> 1][(nt & 1) * 2];
                    const unsigned* blf = &bl[nt >> 1][(nt & 1) * 2];
                    mma_bf16(acc[mt][nt], ah[mt], bhf);
                    mma_bf16(acc[mt][nt], ah[mt], blf);
                    mma_bf16(acc[mt][nt], al[mt], bhf);
                }
        }
        __syncthreads();
        if (c < 3) { STORE_AB(); __syncthreads(); }
    }

    // ---- epilogue: accumulators -> global with bias (uniform branch per warp_n) ----
    #pragma unroll
    for (int mt = 0; mt < 2; mt++)
        #pragma unroll
        for (int nt = 0; nt < 8; nt++) {
            int row = warp_m * 32 + mt * 16 + (lane >> 2);
            int o   = warp_n * 64 + nt * 8 + (lane & 3) * 2;   // 0..127
            float* buf; int col;
            float b0, b1;
            if (o < 64) { col = o;      buf = g_hsrc; b0 = bsrc[col]; b1 = bsrc[col + 1]; }
            else        { col = o - 64; buf = g_hdst; b0 = bdst[col]; b1 = bdst[col + 1]; }
            int n0 = m0 + row, n1 = m0 + row + 8;
            if (n0 < N_NODES)
                *(float2*)(buf + (size_t)n0 * HD + col) =
                    make_float2(acc[mt][nt][0] + b0, acc[mt][nt][1] + b1);
            if (n1 < N_NODES)
                *(float2*)(buf + (size_t)n1 * HD + col) =
                    make_float2(acc[mt][nt][2] + b0, acc[mt][nt][3] + b1);
        }
}

// ---------------- aggregation: one warp per destination node, no atomics ----------------
__global__ __launch_bounds__(256) void agg_kernel(float* __restrict__ out,
                                                  const float* __restrict__ attn)
{
    int warp = (blockIdx.x * blockDim.x + threadIdx.x) >> 5;
    int lane = threadIdx.x & 31;
    if (warp >= N_NODES) return;
    const int d = warp;

    float2 er = ((const float2*)(g_hdst + (size_t)d * HD))[lane];
    float2 aw = ((const float2*)attn)[lane];

    const int start = g_ptr[d];
    const int cnt   = g_deg[d];

    float2 acc = make_float2(0.f, 0.f);
    float  s   = 0.f;

    for (int base = 0; base < cnt; base += 32) {
        int m = cnt - base; if (m > 32) m = 32;
        int sn_l = (lane < m) ? g_asrc[start + base + lane] : 0;
        for (int i = 0; i < m; i++) {
            int sn = __shfl_sync(0xFFFFFFFFu, sn_l, i);
            float2 el = ((const float2*)(g_hsrc + (size_t)sn * HD))[lane];
            float vx = el.x + er.x; vx = (vx > 0.f) ? vx : 0.2f * vx;
            float vy = el.y + er.y; vy = (vy > 0.f) ? vy : 0.2f * vy;
            float p  = vx * aw.x + vy * aw.y;
            p += __shfl_xor_sync(0xFFFFFFFFu, p, 1);
            p += __shfl_xor_sync(0xFFFFFFFFu, p, 2);
            p += __shfl_xor_sync(0xFFFFFFFFu, p, 4);
            float a = __expf(p);
            acc.x += a * el.x;
            acc.y += a * el.y;
            s     += a;
        }
    }

    float inv = (s > 0.f) ? (1.f / s) : 0.f;
    ((float2*)(out + (size_t)d * HD))[lane] = make_float2(acc.x * inv, acc.y * inv);
}

extern "C" void kernel_launch(void* const* d_in, const int* in_sizes, int n_in,
                              void* d_out, int out_size)
{
    const float* feat = (const float*)d_in[0];
    const int*   src  = (const int*)d_in[1];
    const int*   dst  = (const int*)d_in[2];
    const float* Wsrc = (const float*)d_in[3];
    const float* bsrc = (const float*)d_in[4];
    const float* Wdst = (const float*)d_in[5];
    const float* bdst = (const float*)d_in[6];
    const float* attn = (const float*)d_in[7];
    float* out = (float*)d_out;

    cudaFuncSetAttribute(proj_mma_kernel, cudaFuncAttributeMaxDynamicSharedMemorySize, SM_TOT);

    init_deg_kernel<<<(N_NODES + 255) / 256, 256>>>();
    hist_kernel<<<(N_EDGES + 255) / 256, 256>>>(dst);
    scan_kernel<<<1, SCAN_T>>>();
    scatter_kernel<<<(N_EDGES + 255) / 256, 256>>>(src, dst);
    proj_mma_kernel<<<(N_NODES + 127) / 128, 256, SM_TOT>>>(feat, Wsrc, bsrc, Wdst, bdst);
    agg_kernel<<<(N_NODES * 32 + 255) / 256, 256>>>(out, attn);
}

// round 6
// speedup vs baseline: 2.4214x; 1.0807x over previous
#include <cuda_runtime.h>
#include <cuda_bf16.h>
#include <cstdint>

#define N_NODES 50000
#define N_EDGES 800000
#define F_IN    256
#define NH      4
#define HD      64

// ---------------- scratch (device globals; no allocs allowed) ----------------
__device__ float g_hsrc[N_NODES * HD];
__device__ float g_hdst[N_NODES * HD];
__device__ int   g_deg[N_NODES];
__device__ int   g_ptr[N_NODES];
__device__ int   g_cur[N_NODES];
__device__ int   g_asrc[N_EDGES];

// ---------------- CSR build ----------------
__global__ void init_deg_kernel() {
    int i = blockIdx.x * blockDim.x + threadIdx.x;
    if (i < N_NODES) g_deg[i] = 0;
}

// 4 edges per thread for MLP
__global__ void hist_kernel(const int* __restrict__ dst) {
    int base = (blockIdx.x * blockDim.x + threadIdx.x) * 4;
    if (base + 3 < N_EDGES) {
        int4 d = *(const int4*)(dst + base);
        atomicAdd(&g_deg[d.x], 1);
        atomicAdd(&g_deg[d.y], 1);
        atomicAdd(&g_deg[d.z], 1);
        atomicAdd(&g_deg[d.w], 1);
    } else {
        for (int e = base; e < N_EDGES; e++) atomicAdd(&g_deg[dst[e]], 1);
    }
}

#define SCAN_T 1024
#define SCAN_CHUNK 49
__global__ __launch_bounds__(SCAN_T) void scan_kernel() {
    __shared__ int sm[SCAN_T];
    int t = threadIdx.x;
    int lo = t * SCAN_CHUNK;
    int hi = lo + SCAN_CHUNK; if (hi > N_NODES) hi = N_NODES;
    int sum = 0;
    for (int i = lo; i < hi; i++) sum += g_deg[i];
    sm[t] = sum;
    __syncthreads();
    for (int off = 1; off < SCAN_T; off <<= 1) {
        int v = (t >= off) ? sm[t - off] : 0;
        __syncthreads();
        sm[t] += v;
        __syncthreads();
    }
    int run = (t > 0) ? sm[t - 1] : 0;
    for (int i = lo; i < hi; i++) {
        g_ptr[i] = run; g_cur[i] = run;
        run += g_deg[i];
    }
}

// 4 edges per thread for MLP
__global__ void scatter_kernel(const int* __restrict__ src, const int* __restrict__ dst) {
    int base = (blockIdx.x * blockDim.x + threadIdx.x) * 4;
    if (base + 3 < N_EDGES) {
        int4 d = *(const int4*)(dst + base);
        int4 s = *(const int4*)(src + base);
        int p0 = atomicAdd(&g_cur[d.x], 1);
        int p1 = atomicAdd(&g_cur[d.y], 1);
        int p2 = atomicAdd(&g_cur[d.z], 1);
        int p3 = atomicAdd(&g_cur[d.w], 1);
        g_asrc[p0] = s.x; g_asrc[p1] = s.y; g_asrc[p2] = s.z; g_asrc[p3] = s.w;
    } else {
        for (int e = base; e < N_EDGES; e++) {
            int pos = atomicAdd(&g_cur[dst[e]], 1);
            g_asrc[pos] = src[e];
        }
    }
}

// ---------------- helpers ----------------
__device__ __forceinline__ uint32_t smem_u32(const void* p) {
    uint32_t a;
    asm("{ .reg .u64 t; cvta.to.shared.u64 t, %1; cvt.u32.u64 %0, t; }" : "=r"(a) : "l"(p));
    return a;
}
__device__ __forceinline__ void ldsm4(unsigned r[4], uint32_t a) {
    asm volatile("ldmatrix.sync.aligned.m8n8.x4.shared.b16 {%0,%1,%2,%3}, [%4];"
                 : "=r"(r[0]), "=r"(r[1]), "=r"(r[2]), "=r"(r[3]) : "r"(a));
}
__device__ __forceinline__ void mma_bf16(float c[4], const unsigned a[4], const unsigned b[2]) {
    asm volatile(
        "mma.sync.aligned.m16n8k16.row.col.f32.bf16.bf16.f32 "
        "{%0,%1,%2,%3}, {%4,%5,%6,%7}, {%8,%9}, {%0,%1,%2,%3};"
        : "+f"(c[0]), "+f"(c[1]), "+f"(c[2]), "+f"(c[3])
        : "r"(a[0]), "r"(a[1]), "r"(a[2]), "r"(a[3]), "r"(b[0]), "r"(b[1]));
}
__device__ __forceinline__ void cvt8(float4 a, float4 b, uint4& hi, uint4& lo) {
    float xs[8] = {a.x, a.y, a.z, a.w, b.x, b.y, b.z, b.w};
    unsigned h[4], l[4];
    #pragma unroll
    for (int i = 0; i < 4; i++) {
        float x = xs[2 * i], y = xs[2 * i + 1];
        __nv_bfloat16 hx = __float2bfloat16_rn(x);
        __nv_bfloat16 hy = __float2bfloat16_rn(y);
        __nv_bfloat16 lx = __float2bfloat16_rn(x - __bfloat162float(hx));
        __nv_bfloat16 ly = __float2bfloat16_rn(y - __bfloat162float(hy));
        unsigned short uhx = *(unsigned short*)&hx, uhy = *(unsigned short*)&hy;
        unsigned short ulx = *(unsigned short*)&lx, uly = *(unsigned short*)&ly;
        h[i] = (unsigned)uhx | ((unsigned)uhy << 16);
        l[i] = (unsigned)ulx | ((unsigned)uly << 16);
    }
    hi = make_uint4(h[0], h[1], h[2], h[3]);
    lo = make_uint4(l[0], l[1], l[2], l[3]);
}

// ---------------- HMMA bf16-split projection GEMM ----------------
#define RSB    144
#define SA_HI  0
#define SA_LO  18432
#define SB_HI  36864
#define SB_LO  55296
#define SM_TOT 73728

__global__ __launch_bounds__(256, 1)
void proj_mma_kernel(const float* __restrict__ feat,
                     const float* __restrict__ Wsrc, const float* __restrict__ bsrc,
                     const float* __restrict__ Wdst, const float* __restrict__ bdst)
{
    extern __shared__ char smem[];
    const uint32_t sb = smem_u32(smem);
    const int tid  = threadIdx.x;
    const int wid  = tid >> 5, lane = tid & 31;
    const int warp_m = wid & 3;
    const int warp_n = wid >> 2;
    const int m0 = blockIdx.x * 128;

    float acc[2][8][4];
    #pragma unroll
    for (int mt = 0; mt < 2; mt++)
        #pragma unroll
        for (int nt = 0; nt < 8; nt++)
            #pragma unroll
            for (int j = 0; j < 4; j++) acc[mt][nt][j] = 0.0f;

    float4 pa[4][2], pb[4][2];

    #define LOAD_A(c) do {                                                        \
        _Pragma("unroll")                                                         \
        for (int i = 0; i < 4; i++) {                                             \
            int t = tid + i * 256, row = t >> 3, seg = t & 7;                     \
            int node = m0 + row; if (node >= N_NODES) node = N_NODES - 1;         \
            const float* p = feat + (size_t)node * F_IN + (c) * 64 + seg * 8;     \
            pa[i][0] = *(const float4*)p; pa[i][1] = *(const float4*)(p + 4);     \
        } } while (0)

    #define LOAD_B(c) do {                                                        \
        _Pragma("unroll")                                                         \
        for (int i = 0; i < 4; i++) {                                             \
            int t = tid + i * 256, row = t >> 3, seg = t & 7;                     \
            const float* wr = (row < 64) ? (Wsrc + (size_t)row * F_IN)            \
                                         : (Wdst + (size_t)(row - 64) * F_IN);    \
            const float* p = wr + (c) * 64 + seg * 8;                             \
            pb[i][0] = *(const float4*)p; pb[i][1] = *(const float4*)(p + 4);     \
        } } while (0)

    #define STORE_AB() do {                                                       \
        _Pragma("unroll")                                                         \
        for (int i = 0; i < 4; i++) {                                             \
            int t = tid + i * 256, row = t >> 3, seg = t & 7;                     \
            uint32_t off = (uint32_t)(row * RSB + seg * 16);                      \
            uint4 hi, lo;                                                         \
            cvt8(pa[i][0], pa[i][1], hi, lo);                                     \
            *(uint4*)(smem + SA_HI + off) = hi;                                   \
            *(uint4*)(smem + SA_LO + off) = lo;                                   \
            cvt8(pb[i][0], pb[i][1], hi, lo);                                     \
            *(uint4*)(smem + SB_HI + off) = hi;                                   \
            *(uint4*)(smem + SB_LO + off) = lo;                                   \
        } } while (0)

    LOAD_A(0); LOAD_B(0);
    STORE_AB();
    __syncthreads();

    const uint32_t a_base = sb + SA_HI +
        (uint32_t)((warp_m * 32 + (lane & 15)) * RSB + (lane >> 4) * 16);
    const uint32_t b_base = sb + SB_HI +
        (uint32_t)((warp_n * 64 + (lane & 7) + ((lane >> 4) & 1) * 8) * RSB +
                   ((lane >> 3) & 1) * 16);

    for (int c = 0; c < 4; c++) {
        if (c < 3) { LOAD_A(c + 1); LOAD_B(c + 1); }

        #pragma unroll
        for (int ks = 0; ks < 4; ks++) {
            unsigned ah[2][4], al[2][4];
            #pragma unroll
            for (int mt = 0; mt < 2; mt++) {
                ldsm4(ah[mt], a_base + (uint32_t)(mt * 16 * RSB + ks * 32));
                ldsm4(al[mt], a_base + (uint32_t)(18432 + mt * 16 * RSB + ks * 32));
            }
            unsigned bh[4][4], bl[4][4];
            #pragma unroll
            for (int p = 0; p < 4; p++) {
                ldsm4(bh[p], b_base + (uint32_t)(p * 16 * RSB + ks * 32));
                ldsm4(bl[p], b_base + (uint32_t)(18432 + p * 16 * RSB + ks * 32));
            }
            #pragma unroll
            for (int mt = 0; mt < 2; mt++)
                #pragma unroll
                for (int nt = 0; nt < 8; nt++) {
                    const unsigned* bhf = &bh[nt >> 1][(nt & 1) * 2];
                    const unsigned* blf = &bl[nt >> 1][(nt & 1) * 2];
                    mma_bf16(acc[mt][nt], ah[mt], bhf);
                    mma_bf16(acc[mt][nt], ah[mt], blf);
                    mma_bf16(acc[mt][nt], al[mt], bhf);
                }
        }
        __syncthreads();
        if (c < 3) { STORE_AB(); __syncthreads(); }
    }

    #pragma unroll
    for (int mt = 0; mt < 2; mt++)
        #pragma unroll
        for (int nt = 0; nt < 8; nt++) {
            int row = warp_m * 32 + mt * 16 + (lane >> 2);
            int o   = warp_n * 64 + nt * 8 + (lane & 3) * 2;
            float* buf; int col;
            float b0, b1;
            if (o < 64) { col = o;      buf = g_hsrc; b0 = bsrc[col]; b1 = bsrc[col + 1]; }
            else        { col = o - 64; buf = g_hdst; b0 = bdst[col]; b1 = bdst[col + 1]; }
            int n0 = m0 + row, n1 = m0 + row + 8;
            if (n0 < N_NODES)
                *(float2*)(buf + (size_t)n0 * HD + col) =
                    make_float2(acc[mt][nt][0] + b0, acc[mt][nt][1] + b1);
            if (n1 < N_NODES)
                *(float2*)(buf + (size_t)n1 * HD + col) =
                    make_float2(acc[mt][nt][2] + b0, acc[mt][nt][3] + b1);
        }
}

// ---------------- aggregation: one warp per destination node, no atomics ----------------
__global__ __launch_bounds__(256) void agg_kernel(float* __restrict__ out,
                                                  const float* __restrict__ attn)
{
    int warp = (blockIdx.x * blockDim.x + threadIdx.x) >> 5;
    int lane = threadIdx.x & 31;
    if (warp >= N_NODES) return;
    const int d = warp;

    float2 er = ((const float2*)(g_hdst + (size_t)d * HD))[lane];
    float2 aw = ((const float2*)attn)[lane];

    const int start = g_ptr[d];
    const int cnt   = g_deg[d];

    float2 acc = make_float2(0.f, 0.f);
    float  s   = 0.f;

    for (int base = 0; base < cnt; base += 32) {
        int m = cnt - base; if (m > 32) m = 32;
        int sn_l = (lane < m) ? g_asrc[start + base + lane] : 0;
        #pragma unroll 4
        for (int i = 0; i < m; i++) {
            int sn = __shfl_sync(0xFFFFFFFFu, sn_l, i);
            float2 el = ((const float2*)(g_hsrc + (size_t)sn * HD))[lane];
            float vx = el.x + er.x; vx = (vx > 0.f) ? vx : 0.2f * vx;
            float vy = el.y + er.y; vy = (vy > 0.f) ? vy : 0.2f * vy;
            float p  = vx * aw.x + vy * aw.y;
            p += __shfl_xor_sync(0xFFFFFFFFu, p, 1);
            p += __shfl_xor_sync(0xFFFFFFFFu, p, 2);
            p += __shfl_xor_sync(0xFFFFFFFFu, p, 4);
            float a = __expf(p);
            acc.x += a * el.x;
            acc.y += a * el.y;
            s     += a;
        }
    }

    float inv = (s > 0.f) ? (1.f / s) : 0.f;
    ((float2*)(out + (size_t)d * HD))[lane] = make_float2(acc.x * inv, acc.y * inv);
}

extern "C" void kernel_launch(void* const* d_in, const int* in_sizes, int n_in,
                              void* d_out, int out_size)
{
    const float* feat = (const float*)d_in[0];
    const int*   src  = (const int*)d_in[1];
    const int*   dst  = (const int*)d_in[2];
    const float* Wsrc = (const float*)d_in[3];
    const float* bsrc = (const float*)d_in[4];
    const float* Wdst = (const float*)d_in[5];
    const float* bdst = (const float*)d_in[6];
    const float* attn = (const float*)d_in[7];
    float* out = (float*)d_out;

    cudaFuncSetAttribute(proj_mma_kernel, cudaFuncAttributeMaxDynamicSharedMemorySize, SM_TOT);

    // Fork: CSR build (src/dst only) runs concurrently with the projection
    // GEMM (feat/W only). Handles created fresh per call (kernel_launch runs
    // only during correctness + capture); never destroyed, so the captured
    // graph's fork/join nodes stay valid.
    cudaStream_t s2;
    cudaStreamCreateWithFlags(&s2, cudaStreamNonBlocking);
    cudaEvent_t evFork, evJoin;
    cudaEventCreateWithFlags(&evFork, cudaEventDisableTiming);
    cudaEventCreateWithFlags(&evJoin, cudaEventDisableTiming);

    cudaEventRecord(evFork, 0);
    cudaStreamWaitEvent(s2, evFork, 0);

    // CSR branch on s2
    init_deg_kernel<<<(N_NODES + 255) / 256, 256, 0, s2>>>();
    hist_kernel<<<(N_EDGES / 4 + 255) / 256, 256, 0, s2>>>(dst);
    scan_kernel<<<1, SCAN_T, 0, s2>>>();
    scatter_kernel<<<(N_EDGES / 4 + 255) / 256, 256, 0, s2>>>(src, dst);
    cudaEventRecord(evJoin, s2);

    // GEMM branch on capture (default) stream
    proj_mma_kernel<<<(N_NODES + 127) / 128, 256, SM_TOT>>>(feat, Wsrc, bsrc, Wdst, bdst);

    // Join, then aggregate
    cudaStreamWaitEvent(0, evJoin, 0);
    agg_kernel<<<(N_NODES * 32 + 255) / 256, 256>>>(out, attn);
}